// round 2
// baseline (speedup 1.0000x reference)
#include <cuda_runtime.h>
#include <math.h>

#define Bc   8192
#define DIMc 4096
#define Pc   64

typedef unsigned long long ull;

// ---------- packed fp32x2 helpers (Blackwell sm_103a) ----------
__device__ __forceinline__ ull pk2(float x, float y) {
    ull r; asm("mov.b64 %0, {%1, %2};" : "=l"(r) : "f"(x), "f"(y)); return r;
}
__device__ __forceinline__ float2 upk2(ull v) {
    float2 r; asm("mov.b64 {%0, %1}, %2;" : "=f"(r.x), "=f"(r.y) : "l"(v)); return r;
}
__device__ __forceinline__ void ffma2(ull &d, ull a, ull b) {
    asm("fma.rn.f32x2 %0, %1, %2, %0;" : "+l"(d) : "l"(a), "l"(b));
}

// ---------- scratch (allocation-free: static device globals) ----------
__device__ float g_scale[Bc];
__device__ float g_buf1[(size_t)Bc * DIMc];   // pre-LN output
__device__ float g_buf2[(size_t)Bc * DIMc];   // normed

// ============================================================================
// K1: phases + alignment + gain  ->  g_scale[b] = align_sum * softplus(align/64 + 0.5) / 64
// Tile: 32 rows x 128 outputs (64 key + 64 query), K chunked by 64.
// ============================================================================
__global__ void __launch_bounds__(256)
phase_kernel(const float* __restrict__ x,
             const float* __restrict__ Wk, const float* __restrict__ bk,
             const float* __restrict__ Wq, const float* __restrict__ bq,
             float* __restrict__ scale_out)
{
    __shared__ float sm[32*68 + 128*65];      // 41,984 B
    float (*Xs)[68] = (float(*)[68])sm;
    float (*Ws)[65] = (float(*)[65])(sm + 32*68);

    const int tid = threadIdx.x;
    const int b0  = blockIdx.x * 32;
    const int ty  = tid >> 4;      // 0..15 -> row pair 2ty, 2ty+1
    const int tx  = tid & 15;      // 0..15 -> cols tx*8..tx*8+7

    float acc0[8], acc1[8];
#pragma unroll
    for (int j = 0; j < 8; j++) { acc0[j] = 0.f; acc1[j] = 0.f; }

    for (int k0 = 0; k0 < DIMc; k0 += 64) {
        // load X tile 32x64 (float4, padded stride 68 keeps 16B alignment)
#pragma unroll
        for (int r = 0; r < 2; r++) {
            int i = tid + 256 * r;
            int row = i >> 4, c4 = i & 15;
            float4 v = *(const float4*)(x + (size_t)(b0 + row) * DIMc + k0 + c4 * 4);
            *(float4*)&Xs[row][c4 * 4] = v;
        }
        // load W tile 128x64 (rows 0-63 = Wk, 64-127 = Wq); scalar stores (pad 65)
#pragma unroll
        for (int r = 0; r < 8; r++) {
            int i = tid + 256 * r;
            int row = i >> 4, c4 = i & 15;
            const float* src = (row < 64) ? (Wk + (size_t)row * DIMc)
                                          : (Wq + (size_t)(row - 64) * DIMc);
            float4 v = *(const float4*)(src + k0 + c4 * 4);
            Ws[row][c4 * 4 + 0] = v.x;
            Ws[row][c4 * 4 + 1] = v.y;
            Ws[row][c4 * 4 + 2] = v.z;
            Ws[row][c4 * 4 + 3] = v.w;
        }
        __syncthreads();

#pragma unroll 4
        for (int kk = 0; kk < 64; kk++) {
            float a0 = Xs[2 * ty][kk];
            float a1 = Xs[2 * ty + 1][kk];
#pragma unroll
            for (int j = 0; j < 8; j++) {
                float b = Ws[tx * 8 + j][kk];
                acc0[j] += a0 * b;
                acc1[j] += a1 * b;
            }
        }
        __syncthreads();
    }

    // write phases: Ps[row][c], c<64 = key phase, c>=64 = query phase
    float (*Ps)[132] = (float(*)[132])sm;     // reuse (all reads done)
    const float PIf = 3.14159265358979323846f;
#pragma unroll
    for (int j = 0; j < 8; j++) {
        int c = tx * 8 + j;
        float bias = (c < 64) ? __ldg(&bk[c]) : __ldg(&bq[c - 64]);
        Ps[2 * ty][c]     = tanhf(acc0[j] + bias) * PIf;
        Ps[2 * ty + 1][c] = tanhf(acc1[j] + bias) * PIf;
    }
    __syncthreads();

    const int wid = tid >> 5, lane = tid & 31;
#pragma unroll
    for (int rr = 0; rr < 4; rr++) {
        int r = wid * 4 + rr;
        float c = cosf(Ps[r][lane]      - Ps[r][64 + lane]) +
                  cosf(Ps[r][lane + 32] - Ps[r][96 + lane]);
#pragma unroll
        for (int off = 16; off > 0; off >>= 1)
            c += __shfl_xor_sync(0xFFFFFFFFu, c, off);
        if (lane == 0) {
            float align = c;
            float gain  = log1pf(expf(align / 64.f + 0.5f));   // softplus
            scale_out[b0 + r] = align * gain / 64.f;
        }
    }
}

// ============================================================================
// GEMM: out[m][n] = epilogue( sum_k A[m][k] * W[n][k] )
// 128x128x16 tiles, 256 threads, 8x8/thread, packed f32x2 FMA (pairs along M).
// MODE 0: out = (acc + bias[n]) * aux[m]          (aux = g_scale)
// MODE 1: out = aux[m][n] + bias[n] + acc         (aux = residual x)
// ============================================================================
#define BMt 128
#define BNt 128
#define BKt 16
#define LDT (BMt + 4)

__device__ __forceinline__ void mm_step(const float (*Asb)[LDT], const float (*Bsb)[LDT],
                                        ull acc[4][8], int am, int bn)
{
#pragma unroll
    for (int k = 0; k < BKt; k++) {
        ulonglong2 a0 = *(const ulonglong2*)&Asb[k][am];
        ulonglong2 a1 = *(const ulonglong2*)&Asb[k][am + 4];
        float4 f0 = *(const float4*)&Bsb[k][bn];
        float4 f1 = *(const float4*)&Bsb[k][bn + 4];
        float bs[8] = { f0.x, f0.y, f0.z, f0.w, f1.x, f1.y, f1.z, f1.w };
        ull ap0 = a0.x, ap1 = a0.y, ap2 = a1.x, ap3 = a1.y;
#pragma unroll
        for (int j = 0; j < 8; j++) {
            ull bd = pk2(bs[j], bs[j]);
            ffma2(acc[0][j], ap0, bd);
            ffma2(acc[1][j], ap1, bd);
            ffma2(acc[2][j], ap2, bd);
            ffma2(acc[3][j], ap3, bd);
        }
    }
}

template<int MODE>
__global__ void __launch_bounds__(256)
gemm128(const float* __restrict__ A, const float* __restrict__ W,
        const float* __restrict__ bias, const float* __restrict__ aux,
        float* __restrict__ out)
{
    __shared__ float As[2][BKt][LDT];
    __shared__ float Bs[2][BKt][LDT];

    const int tid = threadIdx.x;
    const int lr = tid >> 2;            // 0..63
    const int lc = (tid & 3) << 2;      // 0,4,8,12
    const float* Ag = A + (size_t)(blockIdx.y * BMt + lr) * DIMc + lc;
    const float* Wg = W + (size_t)(blockIdx.x * BNt + lr) * DIMc + lc;
    const size_t half = (size_t)64 * DIMc;

    // stage 0
    {
        float4 a0 = *(const float4*)(Ag);
        float4 a1 = *(const float4*)(Ag + half);
        float4 w0 = *(const float4*)(Wg);
        float4 w1 = *(const float4*)(Wg + half);
        As[0][lc+0][lr] = a0.x; As[0][lc+1][lr] = a0.y; As[0][lc+2][lr] = a0.z; As[0][lc+3][lr] = a0.w;
        As[0][lc+0][lr+64] = a1.x; As[0][lc+1][lr+64] = a1.y; As[0][lc+2][lr+64] = a1.z; As[0][lc+3][lr+64] = a1.w;
        Bs[0][lc+0][lr] = w0.x; Bs[0][lc+1][lr] = w0.y; Bs[0][lc+2][lr] = w0.z; Bs[0][lc+3][lr] = w0.w;
        Bs[0][lc+0][lr+64] = w1.x; Bs[0][lc+1][lr+64] = w1.y; Bs[0][lc+2][lr+64] = w1.z; Bs[0][lc+3][lr+64] = w1.w;
    }
    __syncthreads();

    const int wid = tid >> 5, lane = tid & 31;
    const int am = (wid & 3) * 32 + (lane & 3) * 8;    // 8 rows (4 pairs)
    const int bn = (wid >> 2) * 64 + (lane >> 2) * 8;  // 8 cols

    ull acc[4][8];
#pragma unroll
    for (int p = 0; p < 4; p++)
#pragma unroll
        for (int j = 0; j < 8; j++) acc[p][j] = 0ULL;

    int cur = 0;
    for (int k0 = BKt; k0 < DIMc; k0 += BKt) {
        float4 a0 = *(const float4*)(Ag + k0);
        float4 a1 = *(const float4*)(Ag + half + k0);
        float4 w0 = *(const float4*)(Wg + k0);
        float4 w1 = *(const float4*)(Wg + half + k0);

        mm_step(As[cur], Bs[cur], acc, am, bn);

        const int nxt = cur ^ 1;
        As[nxt][lc+0][lr] = a0.x; As[nxt][lc+1][lr] = a0.y; As[nxt][lc+2][lr] = a0.z; As[nxt][lc+3][lr] = a0.w;
        As[nxt][lc+0][lr+64] = a1.x; As[nxt][lc+1][lr+64] = a1.y; As[nxt][lc+2][lr+64] = a1.z; As[nxt][lc+3][lr+64] = a1.w;
        Bs[nxt][lc+0][lr] = w0.x; Bs[nxt][lc+1][lr] = w0.y; Bs[nxt][lc+2][lr] = w0.z; Bs[nxt][lc+3][lr] = w0.w;
        Bs[nxt][lc+0][lr+64] = w1.x; Bs[nxt][lc+1][lr+64] = w1.y; Bs[nxt][lc+2][lr+64] = w1.z; Bs[nxt][lc+3][lr+64] = w1.w;
        __syncthreads();
        cur = nxt;
    }
    mm_step(As[cur], Bs[cur], acc, am, bn);

    // epilogue
    const int gm = blockIdx.y * BMt + am;
    const int gn = blockIdx.x * BNt + bn;
    float4 b0 = *(const float4*)&bias[gn];
    float4 b1 = *(const float4*)&bias[gn + 4];
    float bb[8] = { b0.x, b0.y, b0.z, b0.w, b1.x, b1.y, b1.z, b1.w };

#pragma unroll
    for (int p = 0; p < 4; p++) {
        const int r0 = gm + 2 * p;
        float o0[8], o1[8];
#pragma unroll
        for (int j = 0; j < 8; j++) { float2 v = upk2(acc[p][j]); o0[j] = v.x; o1[j] = v.y; }

        if (MODE == 0) {
            float s0 = __ldg(&aux[r0]);
            float s1 = __ldg(&aux[r0 + 1]);
#pragma unroll
            for (int j = 0; j < 8; j++) {
                o0[j] = (o0[j] + bb[j]) * s0;
                o1[j] = (o1[j] + bb[j]) * s1;
            }
        } else {
            const float* x0 = aux + (size_t)r0 * DIMc + gn;
            float4 xa = *(const float4*)(x0);
            float4 xb = *(const float4*)(x0 + 4);
            float4 xc = *(const float4*)(x0 + DIMc);
            float4 xd = *(const float4*)(x0 + DIMc + 4);
            float xr0[8] = { xa.x, xa.y, xa.z, xa.w, xb.x, xb.y, xb.z, xb.w };
            float xr1[8] = { xc.x, xc.y, xc.z, xc.w, xd.x, xd.y, xd.z, xd.w };
#pragma unroll
            for (int j = 0; j < 8; j++) {
                o0[j] += bb[j] + xr0[j];
                o1[j] += bb[j] + xr1[j];
            }
        }

        float* po = out + (size_t)r0 * DIMc + gn;
        *(float4*)(po)            = make_float4(o0[0], o0[1], o0[2], o0[3]);
        *(float4*)(po + 4)        = make_float4(o0[4], o0[5], o0[6], o0[7]);
        *(float4*)(po + DIMc)     = make_float4(o1[0], o1[1], o1[2], o1[3]);
        *(float4*)(po + DIMc + 4) = make_float4(o1[4], o1[5], o1[6], o1[7]);
    }
}

// ============================================================================
// K3: row LayerNorm
// ============================================================================
__global__ void __launch_bounds__(256)
ln_kernel(const float* __restrict__ in, const float* __restrict__ g,
          const float* __restrict__ b, float* __restrict__ o)
{
    const int row = blockIdx.x;
    const float* rp = in + (size_t)row * DIMc;
    float* op = o + (size_t)row * DIMc;
    const int t = threadIdx.x;

    float4 v[4];
    float s = 0.f, s2 = 0.f;
#pragma unroll
    for (int i = 0; i < 4; i++) {
        v[i] = *(const float4*)(rp + 4 * (t + 256 * i));
        s  += v[i].x + v[i].y + v[i].z + v[i].w;
        s2 += v[i].x * v[i].x + v[i].y * v[i].y + v[i].z * v[i].z + v[i].w * v[i].w;
    }
#pragma unroll
    for (int off = 16; off > 0; off >>= 1) {
        s  += __shfl_xor_sync(0xFFFFFFFFu, s, off);
        s2 += __shfl_xor_sync(0xFFFFFFFFu, s2, off);
    }
    __shared__ float rs[8], rs2[8];
    __shared__ float mu_s, rstd_s;
    const int wid = t >> 5, lane = t & 31;
    if (lane == 0) { rs[wid] = s; rs2[wid] = s2; }
    __syncthreads();
    if (t == 0) {
        float ts = 0.f, ts2 = 0.f;
#pragma unroll
        for (int i = 0; i < 8; i++) { ts += rs[i]; ts2 += rs2[i]; }
        float mu  = ts / (float)DIMc;
        float var = ts2 / (float)DIMc - mu * mu;
        mu_s   = mu;
        rstd_s = rsqrtf(fmaxf(var, 0.f) + 1e-5f);
    }
    __syncthreads();
    const float mu = mu_s, rstd = rstd_s;
#pragma unroll
    for (int i = 0; i < 4; i++) {
        int c = 4 * (t + 256 * i);
        float4 gg = *(const float4*)(g + c);
        float4 bb = *(const float4*)(b + c);
        float4 ov;
        ov.x = (v[i].x - mu) * rstd * gg.x + bb.x;
        ov.y = (v[i].y - mu) * rstd * gg.y + bb.y;
        ov.z = (v[i].z - mu) * rstd * gg.z + bb.z;
        ov.w = (v[i].w - mu) * rstd * gg.w + bb.w;
        *(float4*)(op + c) = ov;
    }
}

// ============================================================================
// launch
// ============================================================================
extern "C" void kernel_launch(void* const* d_in, const int* in_sizes, int n_in,
                              void* d_out, int out_size)
{
    (void)in_sizes; (void)n_in; (void)out_size;
    const float* x   = (const float*)d_in[0];
    const float* Wk  = (const float*)d_in[1];
    const float* bk  = (const float*)d_in[2];
    const float* Wq  = (const float*)d_in[3];
    const float* bq  = (const float*)d_in[4];
    const float* Wv  = (const float*)d_in[5];
    const float* bv  = (const float*)d_in[6];
    const float* lng = (const float*)d_in[7];
    const float* lnb = (const float*)d_in[8];
    const float* Wo  = (const float*)d_in[9];
    const float* bo  = (const float*)d_in[10];
    float* out = (float*)d_out;

    void *psc_v, *pb1_v, *pb2_v;
    cudaGetSymbolAddress(&psc_v, g_scale);
    cudaGetSymbolAddress(&pb1_v, g_buf1);
    cudaGetSymbolAddress(&pb2_v, g_buf2);
    float* psc = (float*)psc_v;
    float* pb1 = (float*)pb1_v;
    float* pb2 = (float*)pb2_v;

    phase_kernel<<<Bc / 32, 256>>>(x, Wk, bk, Wq, bq, psc);
    gemm128<0><<<dim3(DIMc / BNt, Bc / BMt), 256>>>(x, Wv, bv, psc, pb1);
    ln_kernel<<<Bc, 256>>>(pb1, lng, lnb, pb2);
    gemm128<1><<<dim3(DIMc / BNt, Bc / BMt), 256>>>(pb2, Wo, bo, x, out);
}

// round 5
// speedup vs baseline: 2.8252x; 2.8252x over previous
#include <cuda_runtime.h>
#include <cuda_bf16.h>
#include <math.h>
#include <stdint.h>

#define Bc   8192
#define DIMc 4096
#define Pc   64

// tcgen05 is only available on the arch-specific ('a') compile pass.
#if defined(__CUDA_ARCH__) && (defined(__CUDA_ARCH_FEAT_SM103_ALL) || defined(__CUDA_ARCH_FEAT_SM100_ALL))
#define TC_OK 1
#else
#define TC_OK 0
#endif

// ============================ PTX helpers ====================================
#if TC_OK
__device__ __forceinline__ uint32_t smem_u32(const void* p) {
    uint32_t a;
    asm("{ .reg .u64 t; cvta.to.shared.u64 t, %1; cvt.u32.u64 %0, t; }" : "=r"(a) : "l"(p));
    return a;
}
__device__ __forceinline__ uint32_t elect_one() {
    uint32_t p;
    asm volatile("{\n\t.reg .pred p;\n\telect.sync _|p, 0xFFFFFFFF;\n\tselp.b32 %0, 1, 0, p;\n\t}" : "=r"(p));
    return p;
}
__device__ __forceinline__ void mbar_init(uint32_t a, uint32_t cnt) {
    asm volatile("mbarrier.init.shared.b64 [%0], %1;" :: "r"(a), "r"(cnt) : "memory");
}
__device__ __forceinline__ void mbar_wait(uint32_t a, uint32_t parity) {
    asm volatile(
        "{\n\t.reg .pred P;\n\t"
        "WL_%=:\n\t"
        "mbarrier.try_wait.parity.acquire.cta.shared::cta.b64 P, [%0], %1, 0x989680;\n\t"
        "@P bra WD_%=;\n\t"
        "bra WL_%=;\n\t"
        "WD_%=:\n\t}"
        :: "r"(a), "r"(parity) : "memory");
}
__device__ __forceinline__ void tmem_alloc(uint32_t dst_smem, uint32_t ncols) {
    asm volatile("tcgen05.alloc.cta_group::1.sync.aligned.shared::cta.b32 [%0], %1;"
                 :: "r"(dst_smem), "r"(ncols) : "memory");
}
__device__ __forceinline__ void tmem_dealloc(uint32_t tmem, uint32_t ncols) {
    asm volatile("tcgen05.dealloc.cta_group::1.sync.aligned.b32 %0, %1;" :: "r"(tmem), "r"(ncols));
}
__device__ __forceinline__ void tmem_relinquish() {
    asm volatile("tcgen05.relinquish_alloc_permit.cta_group::1.sync.aligned;");
}
__device__ __forceinline__ void tc_commit(uint32_t mbar) {
    asm volatile("tcgen05.commit.cta_group::1.mbarrier::arrive::one.shared::cluster.b64 [%0];"
                 :: "r"(mbar) : "memory");
}
__device__ __forceinline__ void tc_fence_after() {
    asm volatile("tcgen05.fence::after_thread_sync;" ::: "memory");
}
__device__ __forceinline__ void async_fence() {
    asm volatile("fence.proxy.async.shared::cta;" ::: "memory");
}
__device__ __forceinline__ void mma_f16_ss(uint32_t d, uint64_t ad, uint64_t bd,
                                           uint32_t idesc, uint32_t enable) {
    asm volatile(
        "{\n\t.reg .pred p;\n\t"
        "setp.ne.u32 p, %4, 0;\n\t"
        "tcgen05.mma.cta_group::1.kind::f16 [%0], %1, %2, %3, {%5, %5, %5, %5}, p;\n\t}"
        :: "r"(d), "l"(ad), "l"(bd), "r"(idesc), "r"(enable), "r"(0u) : "memory");
}
#define TC_LD_X32(r, addr) \
    asm volatile( \
        "tcgen05.ld.sync.aligned.32x32b.x32.b32 " \
        "{%0, %1, %2, %3, %4, %5, %6, %7, " \
        " %8, %9, %10, %11, %12, %13, %14, %15, " \
        " %16, %17, %18, %19, %20, %21, %22, %23, " \
        " %24, %25, %26, %27, %28, %29, %30, %31}, [%32];" \
        : "=r"((r)[0]),  "=r"((r)[1]),  "=r"((r)[2]),  "=r"((r)[3]), \
          "=r"((r)[4]),  "=r"((r)[5]),  "=r"((r)[6]),  "=r"((r)[7]), \
          "=r"((r)[8]),  "=r"((r)[9]),  "=r"((r)[10]), "=r"((r)[11]), \
          "=r"((r)[12]), "=r"((r)[13]), "=r"((r)[14]), "=r"((r)[15]), \
          "=r"((r)[16]), "=r"((r)[17]), "=r"((r)[18]), "=r"((r)[19]), \
          "=r"((r)[20]), "=r"((r)[21]), "=r"((r)[22]), "=r"((r)[23]), \
          "=r"((r)[24]), "=r"((r)[25]), "=r"((r)[26]), "=r"((r)[27]), \
          "=r"((r)[28]), "=r"((r)[29]), "=r"((r)[30]), "=r"((r)[31]) \
        : "r"(addr))
#define TC_WAIT_LD() asm volatile("tcgen05.wait::ld.sync.aligned;" ::: "memory")

// SW128 descriptor: layout=2, version=1, SBO=64, LBO=1
__device__ __forceinline__ uint64_t make_desc(uint32_t addr) {
    const uint64_t base = (uint64_t(2) << 61) | (uint64_t(1) << 46)
                        | (uint64_t(64) << 32) | (uint64_t(1) << 16);
    return base | ((uint64_t)(addr >> 4) & 0x3FFF);
}
#endif // TC_OK

#define SWZ(off) ((off) ^ (((off) >> 3) & 0x70))

// ============================ scratch globals ================================
__device__ float g_scale[Bc];
__device__ float g_buf1[(size_t)Bc * DIMc];                 // pre-LN output (fp32)
__device__ __nv_bfloat16 g_xhi[(size_t)Bc * DIMc];
__device__ __nv_bfloat16 g_xlo[(size_t)Bc * DIMc];
__device__ __nv_bfloat16 g_wvhi[(size_t)DIMc * DIMc];
__device__ __nv_bfloat16 g_wvlo[(size_t)DIMc * DIMc];
__device__ __nv_bfloat16 g_wohi[(size_t)DIMc * DIMc];
__device__ __nv_bfloat16 g_wolo[(size_t)DIMc * DIMc];
__device__ __nv_bfloat16 g_nhi[(size_t)Bc * DIMc];
__device__ __nv_bfloat16 g_nlo[(size_t)Bc * DIMc];

// ============================ split fp32 -> bf16 hi/lo =======================
__device__ __forceinline__ void split1(float v, unsigned short &h, unsigned short &l) {
    __nv_bfloat16 hb = __float2bfloat16(v);
    float r = v - __bfloat162float(hb);
    h = __bfloat16_as_ushort(hb);
    l = __bfloat16_as_ushort(__float2bfloat16(r));
}

__global__ void __launch_bounds__(256)
split_kernel(const float* __restrict__ in, __nv_bfloat16* __restrict__ hi,
             __nv_bfloat16* __restrict__ lo, size_t n4)
{
    size_t i = (size_t)blockIdx.x * 256 + threadIdx.x;
    if (i >= n4) return;
    float4 v = ((const float4*)in)[i];
    ushort4 h, l;
    split1(v.x, h.x, l.x); split1(v.y, h.y, l.y);
    split1(v.z, h.z, l.z); split1(v.w, h.w, l.w);
    ((ushort4*)hi)[i] = h;
    ((ushort4*)lo)[i] = l;
}

// ============================ K1: phase / scale ==============================
__global__ void __launch_bounds__(256)
phase_kernel(const float* __restrict__ x,
             const float* __restrict__ Wk, const float* __restrict__ bk,
             const float* __restrict__ Wq, const float* __restrict__ bq,
             float* __restrict__ scale_out)
{
    __shared__ float sm[32*68 + 128*65];
    float (*Xs)[68] = (float(*)[68])sm;
    float (*Ws)[65] = (float(*)[65])(sm + 32*68);

    const int tid = threadIdx.x;
    const int b0  = blockIdx.x * 32;
    const int ty  = tid >> 4;
    const int tx  = tid & 15;

    float acc0[8], acc1[8];
#pragma unroll
    for (int j = 0; j < 8; j++) { acc0[j] = 0.f; acc1[j] = 0.f; }

    for (int k0 = 0; k0 < DIMc; k0 += 64) {
#pragma unroll
        for (int r = 0; r < 2; r++) {
            int i = tid + 256 * r;
            int row = i >> 4, c4 = i & 15;
            float4 v = *(const float4*)(x + (size_t)(b0 + row) * DIMc + k0 + c4 * 4);
            *(float4*)&Xs[row][c4 * 4] = v;
        }
#pragma unroll
        for (int r = 0; r < 8; r++) {
            int i = tid + 256 * r;
            int row = i >> 4, c4 = i & 15;
            const float* src = (row < 64) ? (Wk + (size_t)row * DIMc)
                                          : (Wq + (size_t)(row - 64) * DIMc);
            float4 v = *(const float4*)(src + k0 + c4 * 4);
            Ws[row][c4 * 4 + 0] = v.x;
            Ws[row][c4 * 4 + 1] = v.y;
            Ws[row][c4 * 4 + 2] = v.z;
            Ws[row][c4 * 4 + 3] = v.w;
        }
        __syncthreads();
#pragma unroll 4
        for (int kk = 0; kk < 64; kk++) {
            float a0 = Xs[2 * ty][kk];
            float a1 = Xs[2 * ty + 1][kk];
#pragma unroll
            for (int j = 0; j < 8; j++) {
                float b = Ws[tx * 8 + j][kk];
                acc0[j] += a0 * b;
                acc1[j] += a1 * b;
            }
        }
        __syncthreads();
    }

    float (*Ps)[132] = (float(*)[132])sm;
    const float PIf = 3.14159265358979323846f;
#pragma unroll
    for (int j = 0; j < 8; j++) {
        int c = tx * 8 + j;
        float bias = (c < 64) ? __ldg(&bk[c]) : __ldg(&bq[c - 64]);
        Ps[2 * ty][c]     = tanhf(acc0[j] + bias) * PIf;
        Ps[2 * ty + 1][c] = tanhf(acc1[j] + bias) * PIf;
    }
    __syncthreads();

    const int wid = tid >> 5, lane = tid & 31;
#pragma unroll
    for (int rr = 0; rr < 4; rr++) {
        int r = wid * 4 + rr;
        float c = cosf(Ps[r][lane]      - Ps[r][64 + lane]) +
                  cosf(Ps[r][lane + 32] - Ps[r][96 + lane]);
#pragma unroll
        for (int off = 16; off > 0; off >>= 1)
            c += __shfl_xor_sync(0xFFFFFFFFu, c, off);
        if (lane == 0) {
            float align = c;
            float gain  = log1pf(expf(align / 64.f + 0.5f));
            scale_out[b0 + r] = align * gain / 64.f;
        }
    }
}

// ============================ tcgen05 bf16-split GEMM ========================
// out[m][n] = epilogue( sum_k A[m][k]*W[n][k] ), A/W given as bf16 hi/lo pairs.
// MODE 0: out = (acc + bias[n]) * aux[m]      MODE 1: out = aux[m][n]+bias[n]+acc
#define BM 128
#define BN 256
#define KC 64
#define NCHUNK (DIMc / KC)
#define IDESC_F16 0x08400490u   // F32 accum, BF16xBF16, N=256, M=128

#define ST_A_HI 0
#define ST_A_LO 16384
#define ST_B_HI 32768
#define ST_B_LO 65536
#define STAGE_SZ 98304
#define SM_DATA0 1024
#define SMEM_TOTAL (SM_DATA0 + 2 * STAGE_SZ)    // 197,632 B

template<int MODE>
__global__ void __launch_bounds__(256, 1)
tc_gemm(const __nv_bfloat16* __restrict__ Ahi, const __nv_bfloat16* __restrict__ Alo,
        const __nv_bfloat16* __restrict__ Bhi, const __nv_bfloat16* __restrict__ Blo,
        const float* __restrict__ bias, const float* __restrict__ aux,
        float* __restrict__ out)
{
#if TC_OK
    extern __shared__ __align__(1024) char smem[];
    const uint32_t sb = smem_u32(smem);
    const int tid = threadIdx.x;
    const int wid = tid >> 5;
    const int lid = tid & 31;
    const int m0 = blockIdx.y * BM;
    const int n0 = blockIdx.x * BN;

    if (wid == 0) tmem_alloc(sb + 0, 512);
    if (tid == 0) { mbar_init(sb + 16, 1); mbar_init(sb + 24, 1); }
    __syncthreads();
    uint32_t tmem;
    asm volatile("ld.shared.b32 %0, [%1];" : "=r"(tmem) : "r"(sb + 0));

    int ph0 = 0, ph1 = 0;

    for (int i = 0; i < NCHUNK; i++) {
        const int cur = i & 1;
        char* stage = smem + SM_DATA0 + cur * STAGE_SZ;
        if (i >= 2) {
            if (cur == 0) { mbar_wait(sb + 16, ph0); ph0 ^= 1; }
            else          { mbar_wait(sb + 24, ph1); ph1 ^= 1; }
        }
        const int k0 = i * KC;

        // ---- A tiles: 128 rows x 64 bf16 (hi & lo), 16B units, SW128 store
#pragma unroll
        for (int r = 0; r < 4; r++) {
            int e = tid + 256 * r;
            int row = e >> 3, seg = e & 7;
            size_t go = (size_t)(m0 + row) * DIMc + k0 + seg * 8;
            uint32_t sw = SWZ((uint32_t)(row * 128 + seg * 16));
            *(uint4*)(stage + ST_A_HI + sw) = *(const uint4*)(Ahi + go);
            *(uint4*)(stage + ST_A_LO + sw) = *(const uint4*)(Alo + go);
        }
        // ---- B tiles: 256 rows x 64 bf16 (hi & lo)
#pragma unroll
        for (int r = 0; r < 8; r++) {
            int e = tid + 256 * r;
            int row = e >> 3, seg = e & 7;
            size_t go = (size_t)(n0 + row) * DIMc + k0 + seg * 8;
            uint32_t sw = SWZ((uint32_t)(row * 128 + seg * 16));
            *(uint4*)(stage + ST_B_HI + sw) = *(const uint4*)(Bhi + go);
            *(uint4*)(stage + ST_B_LO + sw) = *(const uint4*)(Blo + go);
        }
        async_fence();
        __syncthreads();

        if (wid == 0) {
            uint32_t sa = sb + SM_DATA0 + cur * STAGE_SZ;
            uint64_t aH = make_desc(sa + ST_A_HI);
            uint64_t aL = make_desc(sa + ST_A_LO);
            uint64_t bH = make_desc(sa + ST_B_HI);
            uint64_t bL = make_desc(sa + ST_B_LO);
            if (elect_one()) {
#pragma unroll
                for (int k = 0; k < 4; k++)
                    mma_f16_ss(tmem, aH + 2 * k, bH + 2 * k, IDESC_F16,
                               (i == 0 && k == 0) ? 0u : 1u);
#pragma unroll
                for (int k = 0; k < 4; k++)
                    mma_f16_ss(tmem, aH + 2 * k, bL + 2 * k, IDESC_F16, 1u);
#pragma unroll
                for (int k = 0; k < 4; k++)
                    mma_f16_ss(tmem, aL + 2 * k, bH + 2 * k, IDESC_F16, 1u);
                tc_commit(sb + 16 + cur * 8);
            }
        }
    }

    // final wait: commit of last chunk implies all prior MMAs complete
    {
        const int lc = (NCHUNK - 1) & 1;
        mbar_wait(sb + 16 + lc * 8, lc ? ph1 : ph0);
    }
    tc_fence_after();

    // ---- epilogue: warps 0-3 read D (128 lanes x 256 fp32 cols) in 32-col slabs
    if (wid < 4) {
        const int row = m0 + wid * 32 + lid;
        float sc = 0.f;
        if (MODE == 0) sc = __ldg(&aux[row]);
#pragma unroll
        for (int cb = 0; cb < 8; cb++) {
            uint32_t r[32];
            TC_LD_X32(r, tmem + cb * 32);
            TC_WAIT_LD();
            const int nc = n0 + cb * 32;
            float o[32];
#pragma unroll
            for (int j = 0; j < 32; j++) o[j] = __uint_as_float(r[j]);

            const float4* bp = (const float4*)(bias + nc);
            if (MODE == 0) {
#pragma unroll
                for (int q = 0; q < 8; q++) {
                    float4 bv4 = bp[q];
                    o[4*q+0] = (o[4*q+0] + bv4.x) * sc;
                    o[4*q+1] = (o[4*q+1] + bv4.y) * sc;
                    o[4*q+2] = (o[4*q+2] + bv4.z) * sc;
                    o[4*q+3] = (o[4*q+3] + bv4.w) * sc;
                }
            } else {
                const float4* xp = (const float4*)(aux + (size_t)row * DIMc + nc);
#pragma unroll
                for (int q = 0; q < 8; q++) {
                    float4 bv4 = bp[q];
                    float4 xv4 = xp[q];
                    o[4*q+0] += bv4.x + xv4.x;
                    o[4*q+1] += bv4.y + xv4.y;
                    o[4*q+2] += bv4.z + xv4.z;
                    o[4*q+3] += bv4.w + xv4.w;
                }
            }
            float4* op = (float4*)(out + (size_t)row * DIMc + nc);
#pragma unroll
            for (int q = 0; q < 8; q++)
                op[q] = make_float4(o[4*q+0], o[4*q+1], o[4*q+2], o[4*q+3]);
        }
    }
    __syncthreads();
    if (wid == 0) {
        tmem_relinquish();
        tmem_dealloc(tmem, 512);
    }
#else
    // Non-'a' arch pass: must never execute on sm_103a (driver prefers the
    // arch-specific cubin). Trap loudly if it ever does.
    asm volatile("trap;");
#endif
}

// ============================ K3: LayerNorm -> bf16 hi/lo ====================
__global__ void __launch_bounds__(256)
ln_kernel(const float* __restrict__ in, const float* __restrict__ g,
          const float* __restrict__ b,
          __nv_bfloat16* __restrict__ ohi, __nv_bfloat16* __restrict__ olo)
{
    const int row = blockIdx.x;
    const float* rp = in + (size_t)row * DIMc;
    const int t = threadIdx.x;

    float4 v[4];
    float s = 0.f, s2 = 0.f;
#pragma unroll
    for (int i = 0; i < 4; i++) {
        v[i] = *(const float4*)(rp + 4 * (t + 256 * i));
        s  += v[i].x + v[i].y + v[i].z + v[i].w;
        s2 += v[i].x * v[i].x + v[i].y * v[i].y + v[i].z * v[i].z + v[i].w * v[i].w;
    }
#pragma unroll
    for (int off = 16; off > 0; off >>= 1) {
        s  += __shfl_xor_sync(0xFFFFFFFFu, s, off);
        s2 += __shfl_xor_sync(0xFFFFFFFFu, s2, off);
    }
    __shared__ float rs[8], rs2[8];
    __shared__ float mu_s, rstd_s;
    const int wid = t >> 5, lane = t & 31;
    if (lane == 0) { rs[wid] = s; rs2[wid] = s2; }
    __syncthreads();
    if (t == 0) {
        float ts = 0.f, ts2 = 0.f;
#pragma unroll
        for (int i = 0; i < 8; i++) { ts += rs[i]; ts2 += rs2[i]; }
        float mu  = ts / (float)DIMc;
        float var = ts2 / (float)DIMc - mu * mu;
        mu_s   = mu;
        rstd_s = rsqrtf(fmaxf(var, 0.f) + 1e-5f);
    }
    __syncthreads();
    const float mu = mu_s, rstd = rstd_s;
#pragma unroll
    for (int i = 0; i < 4; i++) {
        int c = 4 * (t + 256 * i);
        float4 gg = *(const float4*)(g + c);
        float4 bb = *(const float4*)(b + c);
        float4 ov;
        ov.x = (v[i].x - mu) * rstd * gg.x + bb.x;
        ov.y = (v[i].y - mu) * rstd * gg.y + bb.y;
        ov.z = (v[i].z - mu) * rstd * gg.z + bb.z;
        ov.w = (v[i].w - mu) * rstd * gg.w + bb.w;
        ushort4 h, l;
        split1(ov.x, h.x, l.x); split1(ov.y, h.y, l.y);
        split1(ov.z, h.z, l.z); split1(ov.w, h.w, l.w);
        ((ushort4*)(ohi + (size_t)row * DIMc))[c >> 2] = h;
        ((ushort4*)(olo + (size_t)row * DIMc))[c >> 2] = l;
    }
}

// ============================ launch =========================================
extern "C" void kernel_launch(void* const* d_in, const int* in_sizes, int n_in,
                              void* d_out, int out_size)
{
    (void)in_sizes; (void)n_in; (void)out_size;
    const float* x   = (const float*)d_in[0];
    const float* Wk  = (const float*)d_in[1];
    const float* bk  = (const float*)d_in[2];
    const float* Wq  = (const float*)d_in[3];
    const float* bq  = (const float*)d_in[4];
    const float* Wv  = (const float*)d_in[5];
    const float* bv  = (const float*)d_in[6];
    const float* lng = (const float*)d_in[7];
    const float* lnb = (const float*)d_in[8];
    const float* Wo  = (const float*)d_in[9];
    const float* bo  = (const float*)d_in[10];
    float* out = (float*)d_out;

    void *p;
    cudaGetSymbolAddress(&p, g_scale); float* psc = (float*)p;
    cudaGetSymbolAddress(&p, g_buf1);  float* pb1 = (float*)p;
    cudaGetSymbolAddress(&p, g_xhi);   __nv_bfloat16* xhi = (__nv_bfloat16*)p;
    cudaGetSymbolAddress(&p, g_xlo);   __nv_bfloat16* xlo = (__nv_bfloat16*)p;
    cudaGetSymbolAddress(&p, g_wvhi);  __nv_bfloat16* wvhi = (__nv_bfloat16*)p;
    cudaGetSymbolAddress(&p, g_wvlo);  __nv_bfloat16* wvlo = (__nv_bfloat16*)p;
    cudaGetSymbolAddress(&p, g_wohi);  __nv_bfloat16* wohi = (__nv_bfloat16*)p;
    cudaGetSymbolAddress(&p, g_wolo);  __nv_bfloat16* wolo = (__nv_bfloat16*)p;
    cudaGetSymbolAddress(&p, g_nhi);   __nv_bfloat16* nhi = (__nv_bfloat16*)p;
    cudaGetSymbolAddress(&p, g_nlo);   __nv_bfloat16* nlo = (__nv_bfloat16*)p;

    cudaFuncSetAttribute(tc_gemm<0>, cudaFuncAttributeMaxDynamicSharedMemorySize, SMEM_TOTAL);
    cudaFuncSetAttribute(tc_gemm<1>, cudaFuncAttributeMaxDynamicSharedMemorySize, SMEM_TOTAL);

    const size_t nX4 = (size_t)Bc * DIMc / 4;
    const size_t nW4 = (size_t)DIMc * DIMc / 4;

    split_kernel<<<(unsigned)(nX4 / 256), 256>>>(x,  xhi,  xlo,  nX4);
    split_kernel<<<(unsigned)(nW4 / 256), 256>>>(Wv, wvhi, wvlo, nW4);
    split_kernel<<<(unsigned)(nW4 / 256), 256>>>(Wo, wohi, wolo, nW4);

    phase_kernel<<<Bc / 32, 256>>>(x, Wk, bk, Wq, bq, psc);

    tc_gemm<0><<<dim3(DIMc / BN, Bc / BM), 256, SMEM_TOTAL>>>(xhi, xlo, wvhi, wvlo, bv, psc, pb1);
    ln_kernel<<<Bc, 256>>>(pb1, lng, lnb, nhi, nlo);
    tc_gemm<1><<<dim3(DIMc / BN, Bc / BM), 256, SMEM_TOTAL>>>(nhi, nlo, wohi, wolo, bo, x, out);
}

// round 7
// speedup vs baseline: 5.8057x; 2.0550x over previous
#include <cuda_runtime.h>
#include <cuda_bf16.h>
#include <math.h>
#include <stdint.h>

#define Bc   8192
#define DIMc 4096
#define Pc   64

// tcgen05 is only available on the arch-specific ('a') compile pass.
#if defined(__CUDA_ARCH__) && (defined(__CUDA_ARCH_FEAT_SM103_ALL) || defined(__CUDA_ARCH_FEAT_SM100_ALL))
#define TC_OK 1
#else
#define TC_OK 0
#endif

// ============================ PTX helpers ====================================
#if TC_OK
__device__ __forceinline__ uint32_t smem_u32(const void* p) {
    uint32_t a;
    asm("{ .reg .u64 t; cvta.to.shared.u64 t, %1; cvt.u32.u64 %0, t; }" : "=r"(a) : "l"(p));
    return a;
}
__device__ __forceinline__ uint32_t elect_one() {
    uint32_t p;
    asm volatile("{\n\t.reg .pred p;\n\telect.sync _|p, 0xFFFFFFFF;\n\tselp.b32 %0, 1, 0, p;\n\t}" : "=r"(p));
    return p;
}
__device__ __forceinline__ void mbar_init(uint32_t a, uint32_t cnt) {
    asm volatile("mbarrier.init.shared.b64 [%0], %1;" :: "r"(a), "r"(cnt) : "memory");
}
__device__ __forceinline__ void mbar_wait(uint32_t a, uint32_t parity) {
    asm volatile(
        "{\n\t.reg .pred P;\n\t"
        "WL_%=:\n\t"
        "mbarrier.try_wait.parity.acquire.cta.shared::cta.b64 P, [%0], %1, 0x989680;\n\t"
        "@P bra WD_%=;\n\t"
        "bra WL_%=;\n\t"
        "WD_%=:\n\t}"
        :: "r"(a), "r"(parity) : "memory");
}
__device__ __forceinline__ void tmem_alloc(uint32_t dst_smem, uint32_t ncols) {
    asm volatile("tcgen05.alloc.cta_group::1.sync.aligned.shared::cta.b32 [%0], %1;"
                 :: "r"(dst_smem), "r"(ncols) : "memory");
}
__device__ __forceinline__ void tmem_dealloc(uint32_t tmem, uint32_t ncols) {
    asm volatile("tcgen05.dealloc.cta_group::1.sync.aligned.b32 %0, %1;" :: "r"(tmem), "r"(ncols));
}
__device__ __forceinline__ void tmem_relinquish() {
    asm volatile("tcgen05.relinquish_alloc_permit.cta_group::1.sync.aligned;");
}
__device__ __forceinline__ void tc_commit(uint32_t mbar) {
    asm volatile("tcgen05.commit.cta_group::1.mbarrier::arrive::one.shared::cluster.b64 [%0];"
                 :: "r"(mbar) : "memory");
}
__device__ __forceinline__ void tc_fence_after() {
    asm volatile("tcgen05.fence::after_thread_sync;" ::: "memory");
}
__device__ __forceinline__ void async_fence() {
    asm volatile("fence.proxy.async.shared::cta;" ::: "memory");
}
__device__ __forceinline__ void mma_f16_ss(uint32_t d, uint64_t ad, uint64_t bd,
                                           uint32_t idesc, uint32_t enable) {
    asm volatile(
        "{\n\t.reg .pred p;\n\t"
        "setp.ne.u32 p, %4, 0;\n\t"
        "tcgen05.mma.cta_group::1.kind::f16 [%0], %1, %2, %3, {%5, %5, %5, %5}, p;\n\t}"
        :: "r"(d), "l"(ad), "l"(bd), "r"(idesc), "r"(enable), "r"(0u) : "memory");
}
#define TC_LD_X32(r, addr) \
    asm volatile( \
        "tcgen05.ld.sync.aligned.32x32b.x32.b32 " \
        "{%0, %1, %2, %3, %4, %5, %6, %7, " \
        " %8, %9, %10, %11, %12, %13, %14, %15, " \
        " %16, %17, %18, %19, %20, %21, %22, %23, " \
        " %24, %25, %26, %27, %28, %29, %30, %31}, [%32];" \
        : "=r"((r)[0]),  "=r"((r)[1]),  "=r"((r)[2]),  "=r"((r)[3]), \
          "=r"((r)[4]),  "=r"((r)[5]),  "=r"((r)[6]),  "=r"((r)[7]), \
          "=r"((r)[8]),  "=r"((r)[9]),  "=r"((r)[10]), "=r"((r)[11]), \
          "=r"((r)[12]), "=r"((r)[13]), "=r"((r)[14]), "=r"((r)[15]), \
          "=r"((r)[16]), "=r"((r)[17]), "=r"((r)[18]), "=r"((r)[19]), \
          "=r"((r)[20]), "=r"((r)[21]), "=r"((r)[22]), "=r"((r)[23]), \
          "=r"((r)[24]), "=r"((r)[25]), "=r"((r)[26]), "=r"((r)[27]), \
          "=r"((r)[28]), "=r"((r)[29]), "=r"((r)[30]), "=r"((r)[31]) \
        : "r"(addr))
#define TC_WAIT_LD() asm volatile("tcgen05.wait::ld.sync.aligned;" ::: "memory")

// SW128 descriptor: layout=2, version=1, SBO=64, LBO=1
__device__ __forceinline__ uint64_t make_desc(uint32_t addr) {
    const uint64_t base = (uint64_t(2) << 61) | (uint64_t(1) << 46)
                        | (uint64_t(64) << 32) | (uint64_t(1) << 16);
    return base | ((uint64_t)(addr >> 4) & 0x3FFF);
}
#endif // TC_OK

#define SWZ(off) ((off) ^ (((off) >> 3) & 0x70))

// ============================ scratch globals ================================
__device__ float g_scale[Bc];
__device__ float g_buf1[(size_t)Bc * DIMc];                 // pre-LN output (fp32)
__device__ float g_phase[(size_t)Bc * 128];                 // [kz | qz] pre-activation
__device__ float g_bkq[128];
__device__ __nv_bfloat16 g_xhi[(size_t)Bc * DIMc];
__device__ __nv_bfloat16 g_xlo[(size_t)Bc * DIMc];
__device__ __nv_bfloat16 g_wvhi[(size_t)DIMc * DIMc];
__device__ __nv_bfloat16 g_wvlo[(size_t)DIMc * DIMc];
__device__ __nv_bfloat16 g_wohi[(size_t)DIMc * DIMc];
__device__ __nv_bfloat16 g_wolo[(size_t)DIMc * DIMc];
__device__ __nv_bfloat16 g_nhi[(size_t)Bc * DIMc];
__device__ __nv_bfloat16 g_nlo[(size_t)Bc * DIMc];
__device__ __nv_bfloat16 g_wkqhi[(size_t)128 * DIMc];
__device__ __nv_bfloat16 g_wkqlo[(size_t)128 * DIMc];

// ============================ split fp32 -> bf16 hi/lo =======================
__device__ __forceinline__ void split1(float v, unsigned short &h, unsigned short &l) {
    __nv_bfloat16 hb = __float2bfloat16(v);
    float r = v - __bfloat162float(hb);
    h = __bfloat16_as_ushort(hb);
    l = __bfloat16_as_ushort(__float2bfloat16(r));
}

__global__ void __launch_bounds__(256)
split_kernel(const float* __restrict__ in, __nv_bfloat16* __restrict__ hi,
             __nv_bfloat16* __restrict__ lo, size_t n4)
{
    size_t i = (size_t)blockIdx.x * 256 + threadIdx.x;
    if (i >= n4) return;
    float4 v = ((const float4*)in)[i];
    ushort4 h, l;
    split1(v.x, h.x, l.x); split1(v.y, h.y, l.y);
    split1(v.z, h.z, l.z); split1(v.w, h.w, l.w);
    ((ushort4*)hi)[i] = h;
    ((ushort4*)lo)[i] = l;
}

__global__ void prep_bias(const float* __restrict__ bk, const float* __restrict__ bq,
                          float* __restrict__ bkq)
{
    int t = threadIdx.x;
    bkq[t] = (t < 64) ? bk[t] : bq[t - 64];
}

// ============================ tcgen05 bf16-split GEMM ========================
// out[m][n] = epilogue( sum_k A[m][k]*W[n][k] ), A/W given as bf16 hi/lo pairs.
// MODE 0: out = (acc + bias[n]) * aux[m]
// MODE 1: out = aux[m][n] + bias[n] + acc
// MODE 2: out = acc + bias[n]
#define BM 128
#define KC 64
#define NCHUNK (DIMc / KC)
#define SM_DATA0 1024

template<int MODE, int BNv, int OUTW>
__global__ void __launch_bounds__(256, 1)
tc_gemm(const __nv_bfloat16* __restrict__ Ahi, const __nv_bfloat16* __restrict__ Alo,
        const __nv_bfloat16* __restrict__ Bhi, const __nv_bfloat16* __restrict__ Blo,
        const float* __restrict__ bias, const float* __restrict__ aux,
        float* __restrict__ out)
{
#if TC_OK
    constexpr int ST_A_HI = 0;
    constexpr int ST_A_LO = 16384;
    constexpr int ST_B_HI = 32768;
    constexpr int ST_B_LO = 32768 + BNv * 128;
    constexpr int STAGE_SZ = 32768 + 2 * BNv * 128;
    constexpr uint32_t IDESC = 0x08000490u | ((uint32_t)(BNv / 8) << 17);

    extern __shared__ __align__(1024) char smem[];
    const uint32_t sb = smem_u32(smem);
    const int tid = threadIdx.x;
    const int wid = tid >> 5;
    const int lid = tid & 31;
    const int m0 = blockIdx.y * BM;
    const int n0 = blockIdx.x * BNv;

    if (wid == 0) tmem_alloc(sb + 0, 512);
    if (tid == 0) { mbar_init(sb + 16, 1); mbar_init(sb + 24, 1); }
    __syncthreads();
    uint32_t tmem;
    asm volatile("ld.shared.b32 %0, [%1];" : "=r"(tmem) : "r"(sb + 0));

    int ph0 = 0, ph1 = 0;

    for (int i = 0; i < NCHUNK; i++) {
        const int cur = i & 1;
        char* stage = smem + SM_DATA0 + cur * STAGE_SZ;
        if (i >= 2) {
            if (cur == 0) { mbar_wait(sb + 16, ph0); ph0 ^= 1; }
            else          { mbar_wait(sb + 24, ph1); ph1 ^= 1; }
        }
        const int k0 = i * KC;

        // ---- A tiles: 128 rows x 64 bf16 (hi & lo), SW128
#pragma unroll
        for (int r = 0; r < 4; r++) {
            int e = tid + 256 * r;
            int row = e >> 3, seg = e & 7;
            size_t go = (size_t)(m0 + row) * DIMc + k0 + seg * 8;
            uint32_t sw = SWZ((uint32_t)(row * 128 + seg * 16));
            *(uint4*)(stage + ST_A_HI + sw) = *(const uint4*)(Ahi + go);
            *(uint4*)(stage + ST_A_LO + sw) = *(const uint4*)(Alo + go);
        }
        // ---- B tiles: BNv rows x 64 bf16 (hi & lo)
#pragma unroll
        for (int r = 0; r < BNv / 32; r++) {
            int e = tid + 256 * r;
            int row = e >> 3, seg = e & 7;
            size_t go = (size_t)(n0 + row) * DIMc + k0 + seg * 8;
            uint32_t sw = SWZ((uint32_t)(row * 128 + seg * 16));
            *(uint4*)(stage + ST_B_HI + sw) = *(const uint4*)(Bhi + go);
            *(uint4*)(stage + ST_B_LO + sw) = *(const uint4*)(Blo + go);
        }
        async_fence();
        __syncthreads();

        if (wid == 0) {
            uint32_t sa = sb + SM_DATA0 + cur * STAGE_SZ;
            uint64_t aH = make_desc(sa + ST_A_HI);
            uint64_t aL = make_desc(sa + ST_A_LO);
            uint64_t bH = make_desc(sa + ST_B_HI);
            uint64_t bL = make_desc(sa + ST_B_LO);
            if (elect_one()) {
#pragma unroll
                for (int k = 0; k < 4; k++)
                    mma_f16_ss(tmem, aH + 2 * k, bH + 2 * k, IDESC,
                               (i == 0 && k == 0) ? 0u : 1u);
#pragma unroll
                for (int k = 0; k < 4; k++)
                    mma_f16_ss(tmem, aH + 2 * k, bL + 2 * k, IDESC, 1u);
#pragma unroll
                for (int k = 0; k < 4; k++)
                    mma_f16_ss(tmem, aL + 2 * k, bH + 2 * k, IDESC, 1u);
                tc_commit(sb + 16 + cur * 8);
            }
        }
    }

    // final wait: commit of last chunk implies all prior MMAs complete
    {
        const int lc = (NCHUNK - 1) & 1;
        mbar_wait(sb + 16 + lc * 8, lc ? ph1 : ph0);
    }
    tc_fence_after();

    // ---- epilogue: warps 0-3 read D (128 lanes x BNv fp32 cols), 32-col slabs
    if (wid < 4) {
        const int row = m0 + wid * 32 + lid;
        float sc = 0.f;
        if (MODE == 0) sc = __ldg(&aux[row]);
#pragma unroll
        for (int cb = 0; cb < BNv / 32; cb++) {
            uint32_t r[32];
            TC_LD_X32(r, tmem + cb * 32);
            TC_WAIT_LD();
            const int nc = n0 + cb * 32;
            float o[32];
#pragma unroll
            for (int j = 0; j < 32; j++) o[j] = __uint_as_float(r[j]);

            const float4* bp = (const float4*)(bias + nc);
            if (MODE == 0) {
#pragma unroll
                for (int q = 0; q < 8; q++) {
                    float4 bv4 = bp[q];
                    o[4*q+0] = (o[4*q+0] + bv4.x) * sc;
                    o[4*q+1] = (o[4*q+1] + bv4.y) * sc;
                    o[4*q+2] = (o[4*q+2] + bv4.z) * sc;
                    o[4*q+3] = (o[4*q+3] + bv4.w) * sc;
                }
            } else if (MODE == 1) {
                const float4* xp = (const float4*)(aux + (size_t)row * OUTW + nc);
#pragma unroll
                for (int q = 0; q < 8; q++) {
                    float4 bv4 = bp[q];
                    float4 xv4 = xp[q];
                    o[4*q+0] += bv4.x + xv4.x;
                    o[4*q+1] += bv4.y + xv4.y;
                    o[4*q+2] += bv4.z + xv4.z;
                    o[4*q+3] += bv4.w + xv4.w;
                }
            } else {
#pragma unroll
                for (int q = 0; q < 8; q++) {
                    float4 bv4 = bp[q];
                    o[4*q+0] += bv4.x;
                    o[4*q+1] += bv4.y;
                    o[4*q+2] += bv4.z;
                    o[4*q+3] += bv4.w;
                }
            }
            float4* op = (float4*)(out + (size_t)row * OUTW + nc);
#pragma unroll
            for (int q = 0; q < 8; q++)
                op[q] = make_float4(o[4*q+0], o[4*q+1], o[4*q+2], o[4*q+3]);
        }
    }
    __syncthreads();
    if (wid == 0) {
        tmem_relinquish();
        tmem_dealloc(tmem, 512);
    }
#else
    asm volatile("trap;");
#endif
}

// ============================ phase post-process =============================
// z[8192][128] = [x@Wk^T+bk | x@Wq^T+bq]; one warp per row.
__global__ void __launch_bounds__(256)
phase_post(const float* __restrict__ z, float* __restrict__ scale_out)
{
    const int t = threadIdx.x;
    const int warp = t >> 5, lane = t & 31;
    const int row = blockIdx.x * 8 + warp;
    const float* zr = z + (size_t)row * 128;
    const float PIf = 3.14159265358979323846f;

    float zk0 = zr[lane],      zq0 = zr[64 + lane];
    float zk1 = zr[32 + lane], zq1 = zr[96 + lane];
    float c = cosf((tanhf(zk0) - tanhf(zq0)) * PIf)
            + cosf((tanhf(zk1) - tanhf(zq1)) * PIf);
#pragma unroll
    for (int off = 16; off > 0; off >>= 1)
        c += __shfl_xor_sync(0xFFFFFFFFu, c, off);
    if (lane == 0) {
        float align = c;
        float gain  = log1pf(expf(align / 64.f + 0.5f));
        scale_out[row] = align * gain / 64.f;
    }
}

// ============================ K3: LayerNorm -> bf16 hi/lo ====================
__global__ void __launch_bounds__(256)
ln_kernel(const float* __restrict__ in, const float* __restrict__ g,
          const float* __restrict__ b,
          __nv_bfloat16* __restrict__ ohi, __nv_bfloat16* __restrict__ olo)
{
    const int row = blockIdx.x;
    const float* rp = in + (size_t)row * DIMc;
    const int t = threadIdx.x;

    float4 v[4];
    float s = 0.f, s2 = 0.f;
#pragma unroll
    for (int i = 0; i < 4; i++) {
        v[i] = *(const float4*)(rp + 4 * (t + 256 * i));
        s  += v[i].x + v[i].y + v[i].z + v[i].w;
        s2 += v[i].x * v[i].x + v[i].y * v[i].y + v[i].z * v[i].z + v[i].w * v[i].w;
    }
#pragma unroll
    for (int off = 16; off > 0; off >>= 1) {
        s  += __shfl_xor_sync(0xFFFFFFFFu, s, off);
        s2 += __shfl_xor_sync(0xFFFFFFFFu, s2, off);
    }
    __shared__ float rs[8], rs2[8];
    __shared__ float mu_s, rstd_s;
    const int wid = t >> 5, lane = t & 31;
    if (lane == 0) { rs[wid] = s; rs2[wid] = s2; }
    __syncthreads();
    if (t == 0) {
        float ts = 0.f, ts2 = 0.f;
#pragma unroll
        for (int i = 0; i < 8; i++) { ts += rs[i]; ts2 += rs2[i]; }
        float mu  = ts / (float)DIMc;
        float var = ts2 / (float)DIMc - mu * mu;
        mu_s   = mu;
        rstd_s = rsqrtf(fmaxf(var, 0.f) + 1e-5f);
    }
    __syncthreads();
    const float mu = mu_s, rstd = rstd_s;
#pragma unroll
    for (int i = 0; i < 4; i++) {
        int c = 4 * (t + 256 * i);
        float4 gg = *(const float4*)(g + c);
        float4 bb = *(const float4*)(b + c);
        float4 ov;
        ov.x = (v[i].x - mu) * rstd * gg.x + bb.x;
        ov.y = (v[i].y - mu) * rstd * gg.y + bb.y;
        ov.z = (v[i].z - mu) * rstd * gg.z + bb.z;
        ov.w = (v[i].w - mu) * rstd * gg.w + bb.w;
        ushort4 h, l;
        split1(ov.x, h.x, l.x); split1(ov.y, h.y, l.y);
        split1(ov.z, h.z, l.z); split1(ov.w, h.w, l.w);
        ((ushort4*)(ohi + (size_t)row * DIMc))[c >> 2] = h;
        ((ushort4*)(olo + (size_t)row * DIMc))[c >> 2] = l;
    }
}

// ============================ launch =========================================
extern "C" void kernel_launch(void* const* d_in, const int* in_sizes, int n_in,
                              void* d_out, int out_size)
{
    (void)in_sizes; (void)n_in; (void)out_size;
    const float* x   = (const float*)d_in[0];
    const float* Wk  = (const float*)d_in[1];
    const float* bk  = (const float*)d_in[2];
    const float* Wq  = (const float*)d_in[3];
    const float* bq  = (const float*)d_in[4];
    const float* Wv  = (const float*)d_in[5];
    const float* bv  = (const float*)d_in[6];
    const float* lng = (const float*)d_in[7];
    const float* lnb = (const float*)d_in[8];
    const float* Wo  = (const float*)d_in[9];
    const float* bo  = (const float*)d_in[10];
    float* out = (float*)d_out;

    void *p;
    cudaGetSymbolAddress(&p, g_scale); float* psc = (float*)p;
    cudaGetSymbolAddress(&p, g_buf1);  float* pb1 = (float*)p;
    cudaGetSymbolAddress(&p, g_phase); float* pph = (float*)p;
    cudaGetSymbolAddress(&p, g_bkq);   float* pbkq = (float*)p;
    cudaGetSymbolAddress(&p, g_xhi);   __nv_bfloat16* xhi = (__nv_bfloat16*)p;
    cudaGetSymbolAddress(&p, g_xlo);   __nv_bfloat16* xlo = (__nv_bfloat16*)p;
    cudaGetSymbolAddress(&p, g_wvhi);  __nv_bfloat16* wvhi = (__nv_bfloat16*)p;
    cudaGetSymbolAddress(&p, g_wvlo);  __nv_bfloat16* wvlo = (__nv_bfloat16*)p;
    cudaGetSymbolAddress(&p, g_wohi);  __nv_bfloat16* wohi = (__nv_bfloat16*)p;
    cudaGetSymbolAddress(&p, g_wolo);  __nv_bfloat16* wolo = (__nv_bfloat16*)p;
    cudaGetSymbolAddress(&p, g_nhi);   __nv_bfloat16* nhi = (__nv_bfloat16*)p;
    cudaGetSymbolAddress(&p, g_nlo);   __nv_bfloat16* nlo = (__nv_bfloat16*)p;
    cudaGetSymbolAddress(&p, g_wkqhi); __nv_bfloat16* wkqhi = (__nv_bfloat16*)p;
    cudaGetSymbolAddress(&p, g_wkqlo); __nv_bfloat16* wkqlo = (__nv_bfloat16*)p;

    constexpr int SMEM_256 = SM_DATA0 + 2 * (32768 + 2 * 256 * 128);  // 197,632
    constexpr int SMEM_128 = SM_DATA0 + 2 * (32768 + 2 * 128 * 128);  // 132,096
    cudaFuncSetAttribute((tc_gemm<0,256,DIMc>), cudaFuncAttributeMaxDynamicSharedMemorySize, SMEM_256);
    cudaFuncSetAttribute((tc_gemm<1,256,DIMc>), cudaFuncAttributeMaxDynamicSharedMemorySize, SMEM_256);
    cudaFuncSetAttribute((tc_gemm<2,128,128>),  cudaFuncAttributeMaxDynamicSharedMemorySize, SMEM_128);

    const size_t nX4 = (size_t)Bc * DIMc / 4;
    const size_t nW4 = (size_t)DIMc * DIMc / 4;
    const size_t nP4 = (size_t)64 * DIMc / 4;   // one of Wk/Wq

    split_kernel<<<(unsigned)(nX4 / 256), 256>>>(x,  xhi,  xlo,  nX4);
    split_kernel<<<(unsigned)(nW4 / 256), 256>>>(Wv, wvhi, wvlo, nW4);
    split_kernel<<<(unsigned)(nW4 / 256), 256>>>(Wo, wohi, wolo, nW4);
    split_kernel<<<(unsigned)(nP4 / 256), 256>>>(Wk, wkqhi, wkqlo, nP4);
    split_kernel<<<(unsigned)(nP4 / 256), 256>>>(Wq, wkqhi + (size_t)64 * DIMc,
                                                     wkqlo + (size_t)64 * DIMc, nP4);
    prep_bias<<<1, 128>>>(bk, bq, pbkq);

    // phase GEMM: z = x @ [Wk;Wq]^T + bkq   (8192 x 128)
    tc_gemm<2,128,128><<<dim3(1, Bc / BM), 256, SMEM_128>>>(xhi, xlo, wkqhi, wkqlo,
                                                            pbkq, nullptr, pph);
    phase_post<<<Bc / 8, 256>>>(pph, psc);

    tc_gemm<0,256,DIMc><<<dim3(DIMc / 256, Bc / BM), 256, SMEM_256>>>(xhi, xlo, wvhi, wvlo, bv, psc, pb1);
    ln_kernel<<<Bc, 256>>>(pb1, lng, lnb, nhi, nlo);
    tc_gemm<1,256,DIMc><<<dim3(DIMc / 256, Bc / BM), 256, SMEM_256>>>(nhi, nlo, wohi, wolo, bo, x, out);
}